// round 10
// baseline (speedup 1.0000x reference)
#include <cuda_runtime.h>
#include <cstdint>
#include <cstddef>

// Problem constants
#define BB 64
#define TT 512
#define EE 256
#define HH 256
#define G4 1024          // 4*H
#define KT 21

// LSTM partition: per direction, 4 batch-groups x 16 unit-blocks
#define NBG 4
#define NUB 16
#define UPB 16
#define BPB 16

// ---------------------------------------------------------------------------
// Scratch (static __device__ arrays)
// ---------------------------------------------------------------------------
__device__ float d_pre_f[(size_t)BB * TT * G4];
__device__ float d_pre_b[(size_t)BB * TT * G4];
__device__ float d_hallT[(size_t)2 * HH * BB * TT];   // [feat][b*T+t] (R7/R9 layout)
__device__ float d_em   [(size_t)BB * TT * KT];
__device__ float d_hbuf [2][2][NBG][HH * BPB];        // [parity][dir][bg][u*BPB+b]
__device__ float d_lossb[BB];
__device__ unsigned d_bc[2 * NBG];
__device__ unsigned d_bg_gen[2 * NBG];

// fast, saturation-safe sigmoid / tanh (proven output-neutral in R8/R9)
__device__ __forceinline__ float sigf(float x) {
    x = fminf(fmaxf(x, -30.f), 30.f);
    return __fdividef(1.f, 1.f + __expf(-x));
}
__device__ __forceinline__ float tanhf_fast(float x) {
    x = fminf(fmaxf(x, -15.f), 15.f);
    float e = __expf(2.f * x);
    return __fdividef(e - 1.f, e + 1.f);
}

// ---- packed fp32x2 helpers (Blackwell FFMA2 path; exact fp32 per lane) ----
__device__ __forceinline__ unsigned long long pack2(float x, float y) {
    unsigned long long r;
    asm("mov.b64 %0, {%1, %2};" : "=l"(r) : "f"(x), "f"(y));
    return r;
}
__device__ __forceinline__ unsigned long long fma2(unsigned long long a,
                                                   unsigned long long b,
                                                   unsigned long long c) {
    unsigned long long d;
    asm("fma.rn.f32x2 %0, %1, %2, %3;" : "=l"(d) : "l"(a), "l"(b), "l"(c));
    return d;
}
__device__ __forceinline__ void unpack2(unsigned long long v, float& x, float& y) {
    asm("mov.b64 {%0, %1}, %2;" : "=f"(x), "=f"(y) : "l"(v));
}

// ---------------------------------------------------------------------------
// Kernel 0: reset barrier state at the head of every launch (replay-safe).
// ---------------------------------------------------------------------------
__global__ void bar_reset()
{
    int i = threadIdx.x;
    if (i < 2 * NBG) { d_bc[i] = 0u; d_bg_gen[i] = 0u; }
}

// ---------------------------------------------------------------------------
// Kernel 1: pre = emb[x] @ W^T + bias (gathered SGEMM), f32x2 inner product.
// grid (256, 8, 2[dir]), 256 threads. BM=BN=128, BK=16, 8x8/thread.
// ---------------------------------------------------------------------------
__global__ __launch_bounds__(256) void pre_gemm(const int* __restrict__ x,
                                                const float* __restrict__ emb,
                                                const float* __restrict__ wih_f,
                                                const float* __restrict__ b_f,
                                                const float* __restrict__ wih_b,
                                                const float* __restrict__ b_b)
{
    __shared__ __align__(16) float As[16][132];
    __shared__ __align__(16) float Bs[16][132];
    __shared__ int toks[128];

    const int dir = blockIdx.z;
    const float* W    = dir ? wih_b : wih_f;
    const float* bias = dir ? b_b   : b_f;
    float* out        = dir ? d_pre_b : d_pre_f;

    const int tid = threadIdx.x;
    const int m0 = blockIdx.x * 128;
    const int n0 = blockIdx.y * 128;

    if (tid < 128) toks[tid] = x[m0 + tid];
    __syncthreads();

    unsigned long long acc2[8][4];
#pragma unroll
    for (int i = 0; i < 8; i++)
#pragma unroll
        for (int j = 0; j < 4; j++) acc2[i][j] = 0ull;

    const int tx = tid & 15, ty = tid >> 4;
    const int lr = tid >> 1;
    const int lc = (tid & 1) * 8;

    const float* arow = emb + (size_t)toks[lr] * EE + lc;
    const float* brow = W + (size_t)(n0 + lr) * EE + lc;

    float4 va0 = *(const float4*)(arow);
    float4 va1 = *(const float4*)(arow + 4);
    float4 vb0 = *(const float4*)(brow);
    float4 vb1 = *(const float4*)(brow + 4);

    for (int k0 = 0; k0 < EE; k0 += 16) {
        __syncthreads();
        As[lc + 0][lr] = va0.x; As[lc + 1][lr] = va0.y;
        As[lc + 2][lr] = va0.z; As[lc + 3][lr] = va0.w;
        As[lc + 4][lr] = va1.x; As[lc + 5][lr] = va1.y;
        As[lc + 6][lr] = va1.z; As[lc + 7][lr] = va1.w;
        Bs[lc + 0][lr] = vb0.x; Bs[lc + 1][lr] = vb0.y;
        Bs[lc + 2][lr] = vb0.z; Bs[lc + 3][lr] = vb0.w;
        Bs[lc + 4][lr] = vb1.x; Bs[lc + 5][lr] = vb1.y;
        Bs[lc + 6][lr] = vb1.z; Bs[lc + 7][lr] = vb1.w;
        __syncthreads();
        if (k0 + 16 < EE) {
            va0 = *(const float4*)(arow + k0 + 16);
            va1 = *(const float4*)(arow + k0 + 20);
            vb0 = *(const float4*)(brow + k0 + 16);
            vb1 = *(const float4*)(brow + k0 + 20);
        }
#pragma unroll
        for (int kk = 0; kk < 16; kk++) {
            float4 af0 = *(const float4*)&As[kk][ty * 4];
            float4 af1 = *(const float4*)&As[kk][64 + ty * 4];
            ulonglong2 bp01 = *(const ulonglong2*)&Bs[kk][tx * 4];
            ulonglong2 bp23 = *(const ulonglong2*)&Bs[kk][64 + tx * 4];
            float av[8] = { af0.x, af0.y, af0.z, af0.w,
                            af1.x, af1.y, af1.z, af1.w };
#pragma unroll
            for (int i = 0; i < 8; i++) {
                unsigned long long as = pack2(av[i], av[i]);
                acc2[i][0] = fma2(as, bp01.x, acc2[i][0]);
                acc2[i][1] = fma2(as, bp01.y, acc2[i][1]);
                acc2[i][2] = fma2(as, bp23.x, acc2[i][2]);
                acc2[i][3] = fma2(as, bp23.y, acc2[i][3]);
            }
        }
    }

    float bv[8];
#pragma unroll
    for (int j = 0; j < 4; j++) {
        bv[j]     = bias[n0 + tx * 4 + j];
        bv[4 + j] = bias[n0 + 64 + tx * 4 + j];
    }
#pragma unroll
    for (int i = 0; i < 8; i++) {
        float accf[8];
#pragma unroll
        for (int j = 0; j < 4; j++)
            unpack2(acc2[i][j], accf[2 * j], accf[2 * j + 1]);
        int m = m0 + ((i < 4) ? (ty * 4 + i) : (64 + ty * 4 + i - 4));
        float4 o0 = { accf[0] + bv[0], accf[1] + bv[1],
                      accf[2] + bv[2], accf[3] + bv[3] };
        float4 o1 = { accf[4] + bv[4], accf[5] + bv[5],
                      accf[6] + bv[6], accf[7] + bv[7] };
        *(float4*)(out + (size_t)m * G4 + n0 + tx * 4)      = o0;
        *(float4*)(out + (size_t)m * G4 + n0 + 64 + tx * 4) = o1;
    }
}

// ---------------------------------------------------------------------------
// Barrier v2: scoped atomics (no full MEMBAR). HB chain:
// st.hbuf -> bar.sync -> tid0 atom.acq_rel/red.release -> peer ld.acquire.
// Counters zeroed by bar_reset each launch; waits clock64-bounded.
// ---------------------------------------------------------------------------
__device__ __forceinline__ void bar_arrive(int gid)
{
    if (threadIdx.x == 0) {
        unsigned old;
        unsigned* cp = &d_bc[gid];
        asm volatile("atom.acq_rel.gpu.add.u32 %0, [%1], %2;"
                     : "=r"(old) : "l"(cp), "r"(1u) : "memory");
        if (old == NUB - 1) {
            asm volatile("st.relaxed.gpu.u32 [%0], %1;"
                         :: "l"(cp), "r"(0u) : "memory");
            asm volatile("red.release.gpu.add.u32 [%0], %1;"
                         :: "l"(&d_bg_gen[gid]), "r"(1u) : "memory");
        }
    }
}

__device__ __forceinline__ void bar_wait(int gid, unsigned target)
{
    if (threadIdx.x == 0) {
        unsigned* gp = &d_bg_gen[gid];
        long long t0 = clock64();
        int poll = 0;
        unsigned v;
        do {
            asm volatile("ld.acquire.gpu.u32 %0, [%1];"
                         : "=r"(v) : "l"(gp) : "memory");
            if (v >= target) break;
            if (((++poll) & 63) == 0 &&
                (clock64() - t0) > (long long)4000000) break;   // ~2ms
        } while (true);
    }
    __syncthreads();
}

// ---------------------------------------------------------------------------
// Kernel 2: persistent bi-LSTM, f32x2 mainloop.
// 128 blocks x 256 threads; blockIdx.x = dir*64 + bg*16 + ub.
// Whh slice in SMEM as duplicated float2 pairs, layout [k=256][r=64].
// ---------------------------------------------------------------------------
#define W2S 66   // float2 row stride for w2 ([k][r=64] + pad)
// floats: w2 = 256*66*2 = 33792, h = 4096, g = 64*17 = 1088, c = 256
#define LSTM_SMEM_FLOATS (256*W2S*2 + HH*BPB + 64*17 + 256)

__global__ __launch_bounds__(256) void lstm_kernel(const float* __restrict__ whh_f,
                                                   const float* __restrict__ whh_b)
{
    extern __shared__ __align__(16) float sm[];
    float2* w2_s = (float2*)sm;              // [k][r] stride W2S, value (w,w)
    float* h_s = sm + 256 * W2S * 2;         // [k=u 256][b 16]
    float* g_s = h_s + HH * BPB;             // [r=64][b=16] stride 17
    float* c_s = g_s + 64 * 17;              // [q=16][b=16]

    const int tid = threadIdx.x;
    const int dir = blockIdx.x >> 6;
    const int bg  = (blockIdx.x >> 4) & 3;
    const int ub  = blockIdx.x & 15;
    const int gid = dir * NBG + bg;
    const float* whh = dir ? whh_b : whh_f;
    const float* pre = dir ? d_pre_b : d_pre_f;

    // Whh slice -> duplicated pairs, [k][r]; r = q*4+gate (R7 mapping)
    for (int i = tid; i < 64 * 256; i += 256) {
        int r = i >> 8, k = i & 255;
        int q = r >> 2, gate = r & 3;
        float w = whh[(size_t)(gate * HH + ub * UPB + q) * HH + k];
        w2_s[(size_t)k * W2S + r] = make_float2(w, w);
    }
    c_s[tid] = 0.f;
    {
        int q2 = tid >> 4, b = tid & 15;
        d_hbuf[0][dir][bg][(ub * UPB + q2) * BPB + b] = 0.f;
    }
    __syncthreads();
    bar_arrive(gid);

    const int col = tid & 63;               // gate row 0..63 (= q*4+gate)
    const int bh  = tid >> 6;               // 0..3
    const int b0  = bh * 4;
    const int q   = col >> 2, gate = col & 3;
    const int grow = gate * HH + ub * UPB + q;
    const unsigned long long* w2u = (const unsigned long long*)w2_s + col;

    for (int t = 0; t < TT; t++) {
        const int ts = dir ? (TT - 1 - t) : t;

        // prefetch pre-activations (DRAM) BEFORE the barrier wait
        float a0, a1, a2, a3;
        {
            const size_t bglob = (size_t)(bg * BPB + b0);
            a0 = pre[((bglob + 0) * TT + ts) * G4 + grow];
            a1 = pre[((bglob + 1) * TT + ts) * G4 + grow];
            a2 = pre[((bglob + 2) * TT + ts) * G4 + grow];
            a3 = pre[((bglob + 3) * TT + ts) * G4 + grow];
        }

        bar_wait(gid, (unsigned)(t + 1));

        // stage h: contiguous 16KB (layout [u][b] both sides)
        {
            const float4* src4 = (const float4*)d_hbuf[t & 1][dir][bg];
            float4* dst4 = (float4*)h_s;
            for (int idx = tid; idx < (HH * BPB) / 4; idx += 256)
                dst4[idx] = __ldcg(src4 + idx);
        }
        __syncthreads();

        unsigned long long a01 = pack2(a0, a1);
        unsigned long long a23 = pack2(a2, a3);
#pragma unroll 8
        for (int k = 0; k < HH; k++) {
            unsigned long long wv = w2u[(size_t)k * W2S];
            ulonglong2 hv = *(const ulonglong2*)(h_s + k * BPB + b0);
            a01 = fma2(wv, hv.x, a01);
            a23 = fma2(wv, hv.y, a23);
        }
        unpack2(a01, a0, a1);
        unpack2(a23, a2, a3);
        g_s[col * 17 + b0 + 0] = a0;
        g_s[col * 17 + b0 + 1] = a1;
        g_s[col * 17 + b0 + 2] = a2;
        g_s[col * 17 + b0 + 3] = a3;
        __syncthreads();

        // gates: thread -> (unit q2, batch b)
        float hval;
        size_t hallidx;
        {
            int q2 = tid >> 4, b = tid & 15;
            float iv = g_s[(q2 * 4 + 0) * 17 + b];
            float fv = g_s[(q2 * 4 + 1) * 17 + b];
            float gv = g_s[(q2 * 4 + 2) * 17 + b];
            float ov = g_s[(q2 * 4 + 3) * 17 + b];
            float c  = c_s[q2 * BPB + b];
            c = sigf(fv) * c + sigf(iv) * tanhf_fast(gv);
            hval = sigf(ov) * tanhf_fast(c);
            c_s[q2 * BPB + b] = c;
            int u = ub * UPB + q2;
            if (t != TT - 1)
                d_hbuf[(t + 1) & 1][dir][bg][u * BPB + b] = hval;
            hallidx = (size_t)(dir * HH + u) * (BB * TT)
                    + (size_t)(bg * BPB + b) * TT + ts;
        }
        __syncthreads();                       // all hbuf stores done
        if (t != TT - 1) bar_arrive(gid);      // release (tid0, scoped)
        d_hallT[hallidx] = hval;               // off critical path
    }
}

// ---------------------------------------------------------------------------
// Kernel 3: em[row][k] = sum_f hT[f][row]*wc[k][f] + bc (unchanged, measured)
// ---------------------------------------------------------------------------
__global__ __launch_bounds__(256) void em_kernel(const float* __restrict__ wc,
                                                 const float* __restrict__ bc)
{
    __shared__ float wc_s[KT * 512];
    __shared__ float bc_s[KT];
    const int tid = threadIdx.x;
    for (int i = tid; i < KT * 512; i += 256) wc_s[i] = wc[i];
    if (tid < KT) bc_s[tid] = bc[tid];
    __syncthreads();

    const int row = blockIdx.x * 256 + tid;
    const float* hp = d_hallT + row;

    float acc[KT];
#pragma unroll
    for (int k = 0; k < KT; k++) acc[k] = 0.f;

#pragma unroll 8
    for (int f = 0; f < 512; f++) {
        float hv = __ldcg(hp + (size_t)f * (BB * TT));
#pragma unroll
        for (int k = 0; k < KT; k++) acc[k] += hv * wc_s[k * 512 + f];
    }
#pragma unroll
    for (int k = 0; k < KT; k++)
        d_em[(size_t)row * KT + k] = acc[k] + bc_s[k];
}

// ---------------------------------------------------------------------------
// Kernel 4: CRF (unchanged from R9).
// ---------------------------------------------------------------------------
#define CRF_SMEM_BYTES ((441 + 64 + TT * KT) * 4 + TT * KT + 256)

__global__ __launch_bounds__(128) void crf_kernel(const int* __restrict__ y,
                                                  const float* __restrict__ start,
                                                  const float* __restrict__ endv,
                                                  const float* __restrict__ trans,
                                                  float* __restrict__ out,
                                                  int out_elems)
{
    extern __shared__ float csm[];
    float* tr_s = csm;
    float* sc   = csm + 448;
    float* e_s  = csm + 512;
    unsigned char* bp_s = (unsigned char*)(e_s + TT * KT);

    const int b    = blockIdx.x & 63;
    const int mode = blockIdx.x >> 6;
    const int tid  = threadIdx.x;

    for (int i = tid; i < KT * KT; i += 128) tr_s[i] = trans[i];
    {
        const float4* src = (const float4*)(d_em + (size_t)b * TT * KT);
        float4* dst = (float4*)e_s;
        for (int i = tid; i < (TT * KT) / 4; i += 128) dst[i] = src[i];
    }
    __syncthreads();

    const int k = tid;

    if (mode == 0) {
        if (tid < 32) {
            if (k < KT) sc[k] = start[k] + e_s[k];
            __syncwarp();
            for (int t = 1; t < TT; t++) {
                float nb = 0.f; int bi = 0;
                if (k < KT) {
                    float best = -1e30f;
#pragma unroll
                    for (int kp = 0; kp < KT; kp++) {
                        float vs = sc[kp] + tr_s[kp * KT + k];
                        if (vs > best) { best = vs; bi = kp; }
                    }
                    nb = best + e_s[t * KT + k];
                }
                __syncwarp();
                if (k < KT) { sc[k] = nb; bp_s[t * KT + k] = (unsigned char)bi; }
                __syncwarp();
            }
            if (k < KT) sc[k] += endv[k];
            __syncwarp();
            if (k == 0) {
                float best = sc[0]; int last = 0;
                for (int i = 1; i < KT; i++)
                    if (sc[i] > best) { best = sc[i]; last = i; }
                int tag = last;
                out[b * TT + TT - 1] = (float)tag;
                for (int t = TT - 1; t >= 1; t--) {
                    tag = bp_s[t * KT + tag];
                    out[b * TT + t - 1] = (float)tag;
                }
            }
        }
    } else {
        if (tid < 32) {
            if (k < KT) sc[k] = start[k] + e_s[k];
            __syncwarp();
            for (int t = 1; t < TT; t++) {
                float na = 0.f;
                if (k < KT) {
                    float mx = -1e30f;
#pragma unroll
                    for (int kp = 0; kp < KT; kp++)
                        mx = fmaxf(mx, sc[kp] + tr_s[kp * KT + k]);
                    float s = 0.f;
#pragma unroll
                    for (int kp = 0; kp < KT; kp++)
                        s += __expf(sc[kp] + tr_s[kp * KT + k] - mx);
                    na = mx + __logf(s) + e_s[t * KT + k];
                }
                __syncwarp();
                if (k < KT) sc[k] = na;
                __syncwarp();
            }
            if (k < KT) sc[k] += endv[k];
        }
        __syncthreads();

        float part = 0.f;
        for (int t = 1 + tid; t < TT; t += 128) {
            int yp = y[b * TT + t - 1];
            int yc = y[b * TT + t];
            part += tr_s[yp * KT + yc] + e_s[t * KT + yc];
        }
#pragma unroll
        for (int o = 16; o; o >>= 1) part += __shfl_down_sync(0xffffffffu, part, o);
        __shared__ float red[4];
        if ((tid & 31) == 0) red[tid >> 5] = part;
        __syncthreads();

        if (tid == 0) {
            float num = red[0] + red[1] + red[2] + red[3];
            float mx = -1e30f;
            for (int i = 0; i < KT; i++) mx = fmaxf(mx, sc[i]);
            float s = 0.f;
            for (int i = 0; i < KT; i++) s += __expf(sc[i] - mx);
            float z = mx + __logf(s);
            int y0 = y[b * TT];
            int yl = y[b * TT + TT - 1];
            num += start[y0] + e_s[y0] + endv[yl];
            d_lossb[b] = num - z;
        }
    }
}

__global__ void fin_kernel(float* out, int out_elems)
{
    if (out_elems > BB * TT) {
        float s = 0.f;
        for (int i = 0; i < BB; i++) s += d_lossb[i];
        out[BB * TT] = s / (float)BB;
    }
}

// ---------------------------------------------------------------------------
extern "C" void kernel_launch(void* const* d_in, const int* in_sizes, int n_in,
                              void* d_out, int out_size)
{
    const int*   x     = (const int*)d_in[0];
    const int*   y     = (const int*)d_in[1];
    // d_in[2] = masks (all true)
    const float* emb   = (const float*)d_in[3];
    const float* wih_f = (const float*)d_in[4];
    const float* whh_f = (const float*)d_in[5];
    const float* b_f   = (const float*)d_in[6];
    const float* wih_b = (const float*)d_in[7];
    const float* whh_b = (const float*)d_in[8];
    const float* b_b   = (const float*)d_in[9];
    const float* wc    = (const float*)d_in[10];
    const float* bc    = (const float*)d_in[11];
    const float* start = (const float*)d_in[12];
    const float* endv  = (const float*)d_in[13];
    const float* trans = (const float*)d_in[14];
    float* out = (float*)d_out;

    const size_t lstm_smem = LSTM_SMEM_FLOATS * sizeof(float);
    cudaFuncSetAttribute(lstm_kernel,
                         cudaFuncAttributeMaxDynamicSharedMemorySize,
                         (int)lstm_smem);
    cudaFuncSetAttribute(crf_kernel,
                         cudaFuncAttributeMaxDynamicSharedMemorySize,
                         (int)CRF_SMEM_BYTES);

    bar_reset<<<1, 32>>>();
    pre_gemm<<<dim3(256, 8, 2), 256>>>(x, emb, wih_f, b_f, wih_b, b_b);
    lstm_kernel<<<128, 256, lstm_smem>>>(whh_f, whh_b);
    em_kernel<<<128, 256>>>(wc, bc);
    crf_kernel<<<128, 128, CRF_SMEM_BYTES>>>(y, start, endv, trans, out, out_size);
    fin_kernel<<<1, 1>>>(out, out_size);
}

// round 11
// speedup vs baseline: 1.1909x; 1.1909x over previous
#include <cuda_runtime.h>
#include <cstdint>
#include <cstddef>

// Problem constants
#define BB 64
#define TT 512
#define EE 256
#define HH 256
#define G4 1024          // 4*H
#define KT 21

// LSTM partition: per direction, 4 batch-groups x 16 unit-blocks
#define NBG 4
#define NUB 16
#define UPB 16
#define BPB 16

// ---------------------------------------------------------------------------
// Scratch (static __device__ arrays)
// ---------------------------------------------------------------------------
__device__ float d_pre_f[(size_t)BB * TT * G4];
__device__ float d_pre_b[(size_t)BB * TT * G4];
__device__ float d_hallT[(size_t)2 * HH * BB * TT];   // [feat][b*T+t]
__device__ float d_em   [(size_t)BB * TT * KT];
__device__ float d_hbuf [2][2][NBG][HH * BPB];        // [parity][dir][bg][u*BPB+b]
__device__ float d_lossb[BB];
__device__ unsigned d_bc[2 * NBG];
__device__ unsigned d_bg_gen[2 * NBG];

// fast, saturation-safe sigmoid / tanh (proven output-neutral R8/R9/R10)
__device__ __forceinline__ float sigf(float x) {
    x = fminf(fmaxf(x, -30.f), 30.f);
    return __fdividef(1.f, 1.f + __expf(-x));
}
__device__ __forceinline__ float tanhf_fast(float x) {
    x = fminf(fmaxf(x, -15.f), 15.f);
    float e = __expf(2.f * x);
    return __fdividef(e - 1.f, e + 1.f);
}

// ---------------------------------------------------------------------------
// Kernel 0: reset barrier state at the head of every launch (replay-safe).
// ---------------------------------------------------------------------------
__global__ void bar_reset()
{
    int i = threadIdx.x;
    if (i < 2 * NBG) { d_bc[i] = 0u; d_bg_gen[i] = 0u; }
}

// ---------------------------------------------------------------------------
// Kernel 1: pre = emb[x] @ W^T + bias  (R9 version — best measured)
// grid (256, 8, 2[dir]), 256 threads. BM=BN=128, BK=16, 8x8/thread,
// next-tile global loads issued BEFORE current-tile FMA loop.
// ---------------------------------------------------------------------------
__global__ __launch_bounds__(256) void pre_gemm(const int* __restrict__ x,
                                                const float* __restrict__ emb,
                                                const float* __restrict__ wih_f,
                                                const float* __restrict__ b_f,
                                                const float* __restrict__ wih_b,
                                                const float* __restrict__ b_b)
{
    __shared__ float As[16][132];
    __shared__ float Bs[16][132];
    __shared__ int   toks[128];

    const int dir = blockIdx.z;
    const float* W    = dir ? wih_b : wih_f;
    const float* bias = dir ? b_b   : b_f;
    float* out        = dir ? d_pre_b : d_pre_f;

    const int tid = threadIdx.x;
    const int m0 = blockIdx.x * 128;
    const int n0 = blockIdx.y * 128;

    if (tid < 128) toks[tid] = x[m0 + tid];
    __syncthreads();

    float acc[8][8];
#pragma unroll
    for (int i = 0; i < 8; i++)
#pragma unroll
        for (int j = 0; j < 8; j++) acc[i][j] = 0.f;

    const int tx = tid & 15, ty = tid >> 4;
    const int lr = tid >> 1;
    const int lc = (tid & 1) * 8;

    const float* arow = emb + (size_t)toks[lr] * EE + lc;
    const float* brow = W + (size_t)(n0 + lr) * EE + lc;

    float4 va0 = *(const float4*)(arow);
    float4 va1 = *(const float4*)(arow + 4);
    float4 vb0 = *(const float4*)(brow);
    float4 vb1 = *(const float4*)(brow + 4);

    for (int k0 = 0; k0 < EE; k0 += 16) {
        __syncthreads();
        As[lc + 0][lr] = va0.x; As[lc + 1][lr] = va0.y;
        As[lc + 2][lr] = va0.z; As[lc + 3][lr] = va0.w;
        As[lc + 4][lr] = va1.x; As[lc + 5][lr] = va1.y;
        As[lc + 6][lr] = va1.z; As[lc + 7][lr] = va1.w;
        Bs[lc + 0][lr] = vb0.x; Bs[lc + 1][lr] = vb0.y;
        Bs[lc + 2][lr] = vb0.z; Bs[lc + 3][lr] = vb0.w;
        Bs[lc + 4][lr] = vb1.x; Bs[lc + 5][lr] = vb1.y;
        Bs[lc + 6][lr] = vb1.z; Bs[lc + 7][lr] = vb1.w;
        __syncthreads();
        if (k0 + 16 < EE) {
            va0 = *(const float4*)(arow + k0 + 16);
            va1 = *(const float4*)(arow + k0 + 20);
            vb0 = *(const float4*)(brow + k0 + 16);
            vb1 = *(const float4*)(brow + k0 + 20);
        }
#pragma unroll
        for (int kk = 0; kk < 16; kk++) {
            float a[8], b[8];
            *(float4*)(a)     = *(const float4*)&As[kk][ty * 4];
            *(float4*)(a + 4) = *(const float4*)&As[kk][64 + ty * 4];
            *(float4*)(b)     = *(const float4*)&Bs[kk][tx * 4];
            *(float4*)(b + 4) = *(const float4*)&Bs[kk][64 + tx * 4];
#pragma unroll
            for (int i = 0; i < 8; i++)
#pragma unroll
                for (int j = 0; j < 8; j++) acc[i][j] += a[i] * b[j];
        }
    }

    float bv[8];
#pragma unroll
    for (int j = 0; j < 4; j++) {
        bv[j]     = bias[n0 + tx * 4 + j];
        bv[4 + j] = bias[n0 + 64 + tx * 4 + j];
    }
#pragma unroll
    for (int i = 0; i < 8; i++) {
        int m = m0 + ((i < 4) ? (ty * 4 + i) : (64 + ty * 4 + i - 4));
        float4 o0 = { acc[i][0] + bv[0], acc[i][1] + bv[1],
                      acc[i][2] + bv[2], acc[i][3] + bv[3] };
        float4 o1 = { acc[i][4] + bv[4], acc[i][5] + bv[5],
                      acc[i][6] + bv[6], acc[i][7] + bv[7] };
        *(float4*)(out + (size_t)m * G4 + n0 + tx * 4)      = o0;
        *(float4*)(out + (size_t)m * G4 + n0 + 64 + tx * 4) = o1;
    }
}

// ---------------------------------------------------------------------------
// Barrier (R9 version — best measured). Zeroed each launch by bar_reset;
// waits clock64-bounded: malfunction => wrong output, never a hang.
// ---------------------------------------------------------------------------
__device__ __forceinline__ void bar_arrive(int gid)
{
    if (threadIdx.x == 0) {
        __threadfence();
        if (atomicAdd(&d_bc[gid], 1u) == NUB - 1) {
            atomicExch(&d_bc[gid], 0u);
            __threadfence();
            atomicAdd(&d_bg_gen[gid], 1u);
        }
    }
}

__device__ __forceinline__ void bar_wait(int gid, unsigned target)
{
    if (threadIdx.x == 0) {
        volatile unsigned* vg = &d_bg_gen[gid];
        long long t0 = clock64();
        int poll = 0;
        while (*vg < target) {
            if (((++poll) & 255) == 0 &&
                (clock64() - t0) > (long long)4000000) break;   // ~2ms
        }
        __threadfence();
    }
    __syncthreads();
}

// ---------------------------------------------------------------------------
// Kernel 2: persistent bi-LSTM. 128 blocks x 512 threads (k-split).
// blockIdx.x = dir*64 + bg*16 + ub. Thread = (kh in {0,1}) x 64 gate rows
// x 4 batch-quads; each accumulates over half the k range. Partial gates
// summed in the gate phase. 4 warps/SMSP -> latency hiding; FFMA floor
// unchanged (4096 cyc), issue occupancy 3072/4096 leaves stall slack.
// ---------------------------------------------------------------------------
#define WKS 68                          // w_s row stride ([k][row64])
// floats: w 256*68=17408, h 256*16=4096, g2 2*64*17=2176, c 256
#define LSTM_SMEM_FLOATS (256*WKS + HH*BPB + 2*64*17 + 256)

__global__ __launch_bounds__(512) void lstm_kernel(const float* __restrict__ whh_f,
                                                   const float* __restrict__ whh_b)
{
    extern __shared__ float sm[];
    float* w_s  = sm;                    // [k=256][r=64] stride WKS
    float* h_s  = sm + 256 * WKS;        // [u=256][b=16]
    float* g2_s = h_s + HH * BPB;        // [kh=2][r=64][b=16] stride 17
    float* c_s  = g2_s + 2 * 64 * 17;    // [q=16][b=16]

    const int tid = threadIdx.x;
    const int dir = blockIdx.x >> 6;
    const int bg  = (blockIdx.x >> 4) & 3;
    const int ub  = blockIdx.x & 15;
    const int gid = dir * NBG + bg;
    const float* whh = dir ? whh_b : whh_f;
    const float* pre = dir ? d_pre_b : d_pre_f;

    // load Whh slice transposed: w_s[k][r], r = q*4+gate -> whh[gate*H+ub*16+q]
    for (int i = tid; i < 64 * 256; i += 512) {
        int r = i >> 8, k = i & 255;
        int q = r >> 2, gate = r & 3;
        w_s[k * WKS + r] = whh[(size_t)(gate * HH + ub * UPB + q) * HH + k];
    }
    if (tid < 256) {
        c_s[tid] = 0.f;
        int q2 = tid >> 4, b = tid & 15;
        d_hbuf[0][dir][bg][(ub * UPB + q2) * BPB + b] = 0.f;
    }
    __syncthreads();
    bar_arrive(gid);

    const int kh   = tid >> 8;            // 0 or 1: k half
    const int sub  = tid & 255;
    const int col  = sub & 63;            // gate row 0..63
    const int bh   = sub >> 6;            // 0..3
    const int b0   = bh * 4;
    const int q    = col >> 2, gate = col & 3;
    const int grow = gate * HH + ub * UPB + q;
    const int kbeg = kh * 128;

    for (int t = 0; t < TT; t++) {
        const int ts = dir ? (TT - 1 - t) : t;

        // kh=0 threads prefetch pre-activations (DRAM) BEFORE the wait
        float a0 = 0.f, a1 = 0.f, a2 = 0.f, a3 = 0.f;
        if (kh == 0) {
            const size_t bglob = (size_t)(bg * BPB + b0);
            a0 = pre[((bglob + 0) * TT + ts) * G4 + grow];
            a1 = pre[((bglob + 1) * TT + ts) * G4 + grow];
            a2 = pre[((bglob + 2) * TT + ts) * G4 + grow];
            a3 = pre[((bglob + 3) * TT + ts) * G4 + grow];
        }

        bar_wait(gid, (unsigned)(t + 1));

        // stage h: contiguous 16KB, layout [u][b] both sides
        {
            const float4* src4 = (const float4*)d_hbuf[t & 1][dir][bg];
            float4* dst4 = (float4*)h_s;
            for (int idx = tid; idx < (HH * BPB) / 4; idx += 512)
                dst4[idx] = __ldcg(src4 + idx);
        }
        __syncthreads();

#pragma unroll 8
        for (int k = kbeg; k < kbeg + 128; k += 4) {
            float w0 = w_s[(k + 0) * WKS + col];
            float w1 = w_s[(k + 1) * WKS + col];
            float w2 = w_s[(k + 2) * WKS + col];
            float w3 = w_s[(k + 3) * WKS + col];
            float4 h0 = *(const float4*)(h_s + (k + 0) * BPB + b0);
            float4 h1 = *(const float4*)(h_s + (k + 1) * BPB + b0);
            float4 h2 = *(const float4*)(h_s + (k + 2) * BPB + b0);
            float4 h3 = *(const float4*)(h_s + (k + 3) * BPB + b0);
            a0 += w0 * h0.x + w1 * h1.x + w2 * h2.x + w3 * h3.x;
            a1 += w0 * h0.y + w1 * h1.y + w2 * h2.y + w3 * h3.y;
            a2 += w0 * h0.z + w1 * h1.z + w2 * h2.z + w3 * h3.z;
            a3 += w0 * h0.w + w1 * h1.w + w2 * h2.w + w3 * h3.w;
        }
        float* grow_s = g2_s + (kh * 64 + col) * 17;
        grow_s[b0 + 0] = a0;
        grow_s[b0 + 1] = a1;
        grow_s[b0 + 2] = a2;
        grow_s[b0 + 3] = a3;
        __syncthreads();

        // gates: threads [0,256) -> (unit q2, batch b); sum the two k-halves
        float hval = 0.f;
        size_t hallidx = 0;
        if (tid < 256) {
            int q2 = tid >> 4, b = tid & 15;
            float iv = g2_s[(q2 * 4 + 0) * 17 + b] + g2_s[(64 + q2 * 4 + 0) * 17 + b];
            float fv = g2_s[(q2 * 4 + 1) * 17 + b] + g2_s[(64 + q2 * 4 + 1) * 17 + b];
            float gv = g2_s[(q2 * 4 + 2) * 17 + b] + g2_s[(64 + q2 * 4 + 2) * 17 + b];
            float ov = g2_s[(q2 * 4 + 3) * 17 + b] + g2_s[(64 + q2 * 4 + 3) * 17 + b];
            float c  = c_s[q2 * BPB + b];
            c = sigf(fv) * c + sigf(iv) * tanhf_fast(gv);
            hval = sigf(ov) * tanhf_fast(c);
            c_s[q2 * BPB + b] = c;
            int u = ub * UPB + q2;
            if (t != TT - 1)
                d_hbuf[(t + 1) & 1][dir][bg][u * BPB + b] = hval;
            hallidx = (size_t)(dir * HH + u) * (BB * TT)
                    + (size_t)(bg * BPB + b) * TT + ts;
        }
        __syncthreads();                       // hbuf stores complete
        if (t != TT - 1) bar_arrive(gid);
        if (tid < 256) d_hallT[hallidx] = hval;   // off critical path
    }
}

// ---------------------------------------------------------------------------
// Kernel 3: em[row][k] = sum_f hT[f][row]*wc[k][f] + bc (R9, measured)
// ---------------------------------------------------------------------------
__global__ __launch_bounds__(256) void em_kernel(const float* __restrict__ wc,
                                                 const float* __restrict__ bc)
{
    __shared__ float wc_s[KT * 512];
    __shared__ float bc_s[KT];
    const int tid = threadIdx.x;
    for (int i = tid; i < KT * 512; i += 256) wc_s[i] = wc[i];
    if (tid < KT) bc_s[tid] = bc[tid];
    __syncthreads();

    const int row = blockIdx.x * 256 + tid;
    const float* hp = d_hallT + row;

    float acc[KT];
#pragma unroll
    for (int k = 0; k < KT; k++) acc[k] = 0.f;

#pragma unroll 8
    for (int f = 0; f < 512; f++) {
        float hv = __ldcg(hp + (size_t)f * (BB * TT));
#pragma unroll
        for (int k = 0; k < KT; k++) acc[k] += hv * wc_s[k * 512 + f];
    }
#pragma unroll
    for (int k = 0; k < KT; k++)
        d_em[(size_t)row * KT + k] = acc[k] + bc_s[k];
}

// ---------------------------------------------------------------------------
// Kernel 4: CRF (R9, measured).
// ---------------------------------------------------------------------------
#define CRF_SMEM_BYTES ((441 + 64 + TT * KT) * 4 + TT * KT + 256)

__global__ __launch_bounds__(128) void crf_kernel(const int* __restrict__ y,
                                                  const float* __restrict__ start,
                                                  const float* __restrict__ endv,
                                                  const float* __restrict__ trans,
                                                  float* __restrict__ out,
                                                  int out_elems)
{
    extern __shared__ float csm[];
    float* tr_s = csm;
    float* sc   = csm + 448;
    float* e_s  = csm + 512;
    unsigned char* bp_s = (unsigned char*)(e_s + TT * KT);

    const int b    = blockIdx.x & 63;
    const int mode = blockIdx.x >> 6;
    const int tid  = threadIdx.x;

    for (int i = tid; i < KT * KT; i += 128) tr_s[i] = trans[i];
    {
        const float4* src = (const float4*)(d_em + (size_t)b * TT * KT);
        float4* dst = (float4*)e_s;
        for (int i = tid; i < (TT * KT) / 4; i += 128) dst[i] = src[i];
    }
    __syncthreads();

    const int k = tid;

    if (mode == 0) {
        if (tid < 32) {
            if (k < KT) sc[k] = start[k] + e_s[k];
            __syncwarp();
            for (int t = 1; t < TT; t++) {
                float nb = 0.f; int bi = 0;
                if (k < KT) {
                    float best = -1e30f;
#pragma unroll
                    for (int kp = 0; kp < KT; kp++) {
                        float vs = sc[kp] + tr_s[kp * KT + k];
                        if (vs > best) { best = vs; bi = kp; }
                    }
                    nb = best + e_s[t * KT + k];
                }
                __syncwarp();
                if (k < KT) { sc[k] = nb; bp_s[t * KT + k] = (unsigned char)bi; }
                __syncwarp();
            }
            if (k < KT) sc[k] += endv[k];
            __syncwarp();
            if (k == 0) {
                float best = sc[0]; int last = 0;
                for (int i = 1; i < KT; i++)
                    if (sc[i] > best) { best = sc[i]; last = i; }
                int tag = last;
                out[b * TT + TT - 1] = (float)tag;
                for (int t = TT - 1; t >= 1; t--) {
                    tag = bp_s[t * KT + tag];
                    out[b * TT + t - 1] = (float)tag;
                }
            }
        }
    } else {
        if (tid < 32) {
            if (k < KT) sc[k] = start[k] + e_s[k];
            __syncwarp();
            for (int t = 1; t < TT; t++) {
                float na = 0.f;
                if (k < KT) {
                    float mx = -1e30f;
#pragma unroll
                    for (int kp = 0; kp < KT; kp++)
                        mx = fmaxf(mx, sc[kp] + tr_s[kp * KT + k]);
                    float s = 0.f;
#pragma unroll
                    for (int kp = 0; kp < KT; kp++)
                        s += __expf(sc[kp] + tr_s[kp * KT + k] - mx);
                    na = mx + __logf(s) + e_s[t * KT + k];
                }
                __syncwarp();
                if (k < KT) sc[k] = na;
                __syncwarp();
            }
            if (k < KT) sc[k] += endv[k];
        }
        __syncthreads();

        float part = 0.f;
        for (int t = 1 + tid; t < TT; t += 128) {
            int yp = y[b * TT + t - 1];
            int yc = y[b * TT + t];
            part += tr_s[yp * KT + yc] + e_s[t * KT + yc];
        }
#pragma unroll
        for (int o = 16; o; o >>= 1) part += __shfl_down_sync(0xffffffffu, part, o);
        __shared__ float red[4];
        if ((tid & 31) == 0) red[tid >> 5] = part;
        __syncthreads();

        if (tid == 0) {
            float num = red[0] + red[1] + red[2] + red[3];
            float mx = -1e30f;
            for (int i = 0; i < KT; i++) mx = fmaxf(mx, sc[i]);
            float s = 0.f;
            for (int i = 0; i < KT; i++) s += __expf(sc[i] - mx);
            float z = mx + __logf(s);
            int y0 = y[b * TT];
            int yl = y[b * TT + TT - 1];
            num += start[y0] + e_s[y0] + endv[yl];
            d_lossb[b] = num - z;
        }
    }
}

__global__ void fin_kernel(float* out, int out_elems)
{
    if (out_elems > BB * TT) {
        float s = 0.f;
        for (int i = 0; i < BB; i++) s += d_lossb[i];
        out[BB * TT] = s / (float)BB;
    }
}

// ---------------------------------------------------------------------------
extern "C" void kernel_launch(void* const* d_in, const int* in_sizes, int n_in,
                              void* d_out, int out_size)
{
    const int*   x     = (const int*)d_in[0];
    const int*   y     = (const int*)d_in[1];
    // d_in[2] = masks (all true)
    const float* emb   = (const float*)d_in[3];
    const float* wih_f = (const float*)d_in[4];
    const float* whh_f = (const float*)d_in[5];
    const float* b_f   = (const float*)d_in[6];
    const float* wih_b = (const float*)d_in[7];
    const float* whh_b = (const float*)d_in[8];
    const float* b_b   = (const float*)d_in[9];
    const float* wc    = (const float*)d_in[10];
    const float* bc    = (const float*)d_in[11];
    const float* start = (const float*)d_in[12];
    const float* endv  = (const float*)d_in[13];
    const float* trans = (const float*)d_in[14];
    float* out = (float*)d_out;

    const size_t lstm_smem = LSTM_SMEM_FLOATS * sizeof(float);
    cudaFuncSetAttribute(lstm_kernel,
                         cudaFuncAttributeMaxDynamicSharedMemorySize,
                         (int)lstm_smem);
    cudaFuncSetAttribute(crf_kernel,
                         cudaFuncAttributeMaxDynamicSharedMemorySize,
                         (int)CRF_SMEM_BYTES);

    bar_reset<<<1, 32>>>();
    pre_gemm<<<dim3(256, 8, 2), 256>>>(x, emb, wih_f, b_f, wih_b, b_b);
    lstm_kernel<<<128, 512, lstm_smem>>>(whh_f, whh_b);
    em_kernel<<<128, 256>>>(wc, bc);
    crf_kernel<<<128, 128, CRF_SMEM_BYTES>>>(y, start, endv, trans, out, out_size);
    fin_kernel<<<1, 1>>>(out, out_size);
}

// round 12
// speedup vs baseline: 1.2202x; 1.0246x over previous
#include <cuda_runtime.h>
#include <cstdint>
#include <cstddef>

// Problem constants
#define BB 64
#define TT 512
#define EE 256
#define HH 256
#define G4 1024          // 4*H
#define KT 21

// LSTM partition: per direction, 4 batch-groups x 16 unit-blocks
#define NBG 4
#define NUB 16
#define UPB 16
#define BPB 16
#define KSP 4            // k-split factor (1024 threads)

// ---------------------------------------------------------------------------
// Scratch (static __device__ arrays)
// ---------------------------------------------------------------------------
__device__ float d_pre_f[(size_t)BB * TT * G4];
__device__ float d_pre_b[(size_t)BB * TT * G4];
__device__ float d_hallT[(size_t)2 * HH * BB * TT];   // [feat][b*T+t]
__device__ float d_em   [(size_t)BB * TT * KT];
__device__ float d_hbuf [2][2][NBG][HH * BPB];        // [parity][dir][bg][u*BPB+b]
__device__ float d_lossb[BB];
__device__ unsigned d_bc[2 * NBG];
__device__ unsigned d_bg_gen[2 * NBG];

// fast, saturation-safe sigmoid / tanh (proven output-neutral R8-R11)
__device__ __forceinline__ float sigf(float x) {
    x = fminf(fmaxf(x, -30.f), 30.f);
    return __fdividef(1.f, 1.f + __expf(-x));
}
__device__ __forceinline__ float tanhf_fast(float x) {
    x = fminf(fmaxf(x, -15.f), 15.f);
    float e = __expf(2.f * x);
    return __fdividef(e - 1.f, e + 1.f);
}

// ---------------------------------------------------------------------------
// Kernel 0: reset barrier state (replay-safe).  Kernel 0b: nop spacer so the
// fixed ncu capture slot (-s 5) lands on lstm_kernel instead of em_kernel.
// ---------------------------------------------------------------------------
__global__ void bar_reset()
{
    int i = threadIdx.x;
    if (i < 2 * NBG) { d_bc[i] = 0u; d_bg_gen[i] = 0u; }
}
__global__ void nop_kernel() {}

// ---------------------------------------------------------------------------
// Kernel 1: pre = emb[x] @ W^T + bias  (R9/R11 version — best measured)
// ---------------------------------------------------------------------------
__global__ __launch_bounds__(256) void pre_gemm(const int* __restrict__ x,
                                                const float* __restrict__ emb,
                                                const float* __restrict__ wih_f,
                                                const float* __restrict__ b_f,
                                                const float* __restrict__ wih_b,
                                                const float* __restrict__ b_b)
{
    __shared__ float As[16][132];
    __shared__ float Bs[16][132];
    __shared__ int   toks[128];

    const int dir = blockIdx.z;
    const float* W    = dir ? wih_b : wih_f;
    const float* bias = dir ? b_b   : b_f;
    float* out        = dir ? d_pre_b : d_pre_f;

    const int tid = threadIdx.x;
    const int m0 = blockIdx.x * 128;
    const int n0 = blockIdx.y * 128;

    if (tid < 128) toks[tid] = x[m0 + tid];
    __syncthreads();

    float acc[8][8];
#pragma unroll
    for (int i = 0; i < 8; i++)
#pragma unroll
        for (int j = 0; j < 8; j++) acc[i][j] = 0.f;

    const int tx = tid & 15, ty = tid >> 4;
    const int lr = tid >> 1;
    const int lc = (tid & 1) * 8;

    const float* arow = emb + (size_t)toks[lr] * EE + lc;
    const float* brow = W + (size_t)(n0 + lr) * EE + lc;

    float4 va0 = *(const float4*)(arow);
    float4 va1 = *(const float4*)(arow + 4);
    float4 vb0 = *(const float4*)(brow);
    float4 vb1 = *(const float4*)(brow + 4);

    for (int k0 = 0; k0 < EE; k0 += 16) {
        __syncthreads();
        As[lc + 0][lr] = va0.x; As[lc + 1][lr] = va0.y;
        As[lc + 2][lr] = va0.z; As[lc + 3][lr] = va0.w;
        As[lc + 4][lr] = va1.x; As[lc + 5][lr] = va1.y;
        As[lc + 6][lr] = va1.z; As[lc + 7][lr] = va1.w;
        Bs[lc + 0][lr] = vb0.x; Bs[lc + 1][lr] = vb0.y;
        Bs[lc + 2][lr] = vb0.z; Bs[lc + 3][lr] = vb0.w;
        Bs[lc + 4][lr] = vb1.x; Bs[lc + 5][lr] = vb1.y;
        Bs[lc + 6][lr] = vb1.z; Bs[lc + 7][lr] = vb1.w;
        __syncthreads();
        if (k0 + 16 < EE) {
            va0 = *(const float4*)(arow + k0 + 16);
            va1 = *(const float4*)(arow + k0 + 20);
            vb0 = *(const float4*)(brow + k0 + 16);
            vb1 = *(const float4*)(brow + k0 + 20);
        }
#pragma unroll
        for (int kk = 0; kk < 16; kk++) {
            float a[8], b[8];
            *(float4*)(a)     = *(const float4*)&As[kk][ty * 4];
            *(float4*)(a + 4) = *(const float4*)&As[kk][64 + ty * 4];
            *(float4*)(b)     = *(const float4*)&Bs[kk][tx * 4];
            *(float4*)(b + 4) = *(const float4*)&Bs[kk][64 + tx * 4];
#pragma unroll
            for (int i = 0; i < 8; i++)
#pragma unroll
                for (int j = 0; j < 8; j++) acc[i][j] += a[i] * b[j];
        }
    }

    float bv[8];
#pragma unroll
    for (int j = 0; j < 4; j++) {
        bv[j]     = bias[n0 + tx * 4 + j];
        bv[4 + j] = bias[n0 + 64 + tx * 4 + j];
    }
#pragma unroll
    for (int i = 0; i < 8; i++) {
        int m = m0 + ((i < 4) ? (ty * 4 + i) : (64 + ty * 4 + i - 4));
        float4 o0 = { acc[i][0] + bv[0], acc[i][1] + bv[1],
                      acc[i][2] + bv[2], acc[i][3] + bv[3] };
        float4 o1 = { acc[i][4] + bv[4], acc[i][5] + bv[5],
                      acc[i][6] + bv[6], acc[i][7] + bv[7] };
        *(float4*)(out + (size_t)m * G4 + n0 + tx * 4)      = o0;
        *(float4*)(out + (size_t)m * G4 + n0 + 64 + tx * 4) = o1;
    }
}

// ---------------------------------------------------------------------------
// Barrier (R9/R11 version — best measured). Zeroed each launch by bar_reset;
// waits clock64-bounded: malfunction => wrong output, never a hang.
// ---------------------------------------------------------------------------
__device__ __forceinline__ void bar_arrive(int gid)
{
    if (threadIdx.x == 0) {
        __threadfence();
        if (atomicAdd(&d_bc[gid], 1u) == NUB - 1) {
            atomicExch(&d_bc[gid], 0u);
            __threadfence();
            atomicAdd(&d_bg_gen[gid], 1u);
        }
    }
}

__device__ __forceinline__ void bar_wait(int gid, unsigned target)
{
    if (threadIdx.x == 0) {
        volatile unsigned* vg = &d_bg_gen[gid];
        long long t0 = clock64();
        int poll = 0;
        while (*vg < target) {
            if (((++poll) & 255) == 0 &&
                (clock64() - t0) > (long long)4000000) break;   // ~2ms
        }
        __threadfence();
    }
    __syncthreads();
}

// ---------------------------------------------------------------------------
// Kernel 2: persistent bi-LSTM. 128 blocks x 1024 threads (k-split 4).
// blockIdx.x = dir*64 + bg*16 + ub. Thread = (kh in 0..3) x 64 gate rows
// x 4 batch-quads; each accumulates a quarter of the k range. Partial gates
// summed in the gate phase. 8 warps/SMSP; FFMA floor unchanged (4096 cyc).
// ---------------------------------------------------------------------------
#define WKS 68
// floats: w 256*68=17408, h 256*16=4096, g4 4*64*17=4352, c 256
#define LSTM_SMEM_FLOATS (256*WKS + HH*BPB + KSP*64*17 + 256)

__global__ __launch_bounds__(1024) void lstm_kernel(const float* __restrict__ whh_f,
                                                    const float* __restrict__ whh_b)
{
    extern __shared__ float sm[];
    float* w_s  = sm;                    // [k=256][r=64] stride WKS
    float* h_s  = sm + 256 * WKS;        // [u=256][b=16]
    float* g4_s = h_s + HH * BPB;        // [kh=4][r=64][b=16] stride 17
    float* c_s  = g4_s + KSP * 64 * 17;  // [q=16][b=16]

    const int tid = threadIdx.x;
    const int dir = blockIdx.x >> 6;
    const int bg  = (blockIdx.x >> 4) & 3;
    const int ub  = blockIdx.x & 15;
    const int gid = dir * NBG + bg;
    const float* whh = dir ? whh_b : whh_f;
    const float* pre = dir ? d_pre_b : d_pre_f;

    // load Whh slice transposed: w_s[k][r], r = q*4+gate -> whh[gate*H+ub*16+q]
    for (int i = tid; i < 64 * 256; i += 1024) {
        int r = i >> 8, k = i & 255;
        int q = r >> 2, gate = r & 3;
        w_s[k * WKS + r] = whh[(size_t)(gate * HH + ub * UPB + q) * HH + k];
    }
    if (tid < 256) {
        c_s[tid] = 0.f;
        int q2 = tid >> 4, b = tid & 15;
        d_hbuf[0][dir][bg][(ub * UPB + q2) * BPB + b] = 0.f;
    }
    __syncthreads();
    bar_arrive(gid);

    const int kh   = tid >> 8;            // 0..3: k quarter
    const int sub  = tid & 255;
    const int col  = sub & 63;            // gate row 0..63
    const int bh   = sub >> 6;            // 0..3
    const int b0   = bh * 4;
    const int q    = col >> 2, gate = col & 3;
    const int grow = gate * HH + ub * UPB + q;
    const int kbeg = kh * 64;

    for (int t = 0; t < TT; t++) {
        const int ts = dir ? (TT - 1 - t) : t;

        // kh=0 threads prefetch pre-activations (DRAM) BEFORE the wait
        float a0 = 0.f, a1 = 0.f, a2 = 0.f, a3 = 0.f;
        if (kh == 0) {
            const size_t bglob = (size_t)(bg * BPB + b0);
            a0 = pre[((bglob + 0) * TT + ts) * G4 + grow];
            a1 = pre[((bglob + 1) * TT + ts) * G4 + grow];
            a2 = pre[((bglob + 2) * TT + ts) * G4 + grow];
            a3 = pre[((bglob + 3) * TT + ts) * G4 + grow];
        }

        bar_wait(gid, (unsigned)(t + 1));

        // stage h: contiguous 16KB, layout [u][b] both sides; 1 float4/thread
        {
            const float4* src4 = (const float4*)d_hbuf[t & 1][dir][bg];
            float4* dst4 = (float4*)h_s;
            int idx = tid;                 // 1024 threads, 1024 float4
            dst4[idx] = __ldcg(src4 + idx);
        }
        __syncthreads();

#pragma unroll 8
        for (int k = kbeg; k < kbeg + 64; k += 4) {
            float w0 = w_s[(k + 0) * WKS + col];
            float w1 = w_s[(k + 1) * WKS + col];
            float w2 = w_s[(k + 2) * WKS + col];
            float w3 = w_s[(k + 3) * WKS + col];
            float4 h0 = *(const float4*)(h_s + (k + 0) * BPB + b0);
            float4 h1 = *(const float4*)(h_s + (k + 1) * BPB + b0);
            float4 h2 = *(const float4*)(h_s + (k + 2) * BPB + b0);
            float4 h3 = *(const float4*)(h_s + (k + 3) * BPB + b0);
            a0 += w0 * h0.x + w1 * h1.x + w2 * h2.x + w3 * h3.x;
            a1 += w0 * h0.y + w1 * h1.y + w2 * h2.y + w3 * h3.y;
            a2 += w0 * h0.z + w1 * h1.z + w2 * h2.z + w3 * h3.z;
            a3 += w0 * h0.w + w1 * h1.w + w2 * h2.w + w3 * h3.w;
        }
        {
            float* gr = g4_s + (kh * 64 + col) * 17;
            gr[b0 + 0] = a0;
            gr[b0 + 1] = a1;
            gr[b0 + 2] = a2;
            gr[b0 + 3] = a3;
        }
        __syncthreads();

        // gates: threads [0,256) -> (unit q2, batch b); sum the 4 k-quarters
        float hval = 0.f;
        size_t hallidx = 0;
        if (tid < 256) {
            int q2 = tid >> 4, b = tid & 15;
            float gv4[4];
#pragma unroll
            for (int g = 0; g < 4; g++) {
                int r = q2 * 4 + g;
                gv4[g] = g4_s[r * 17 + b]
                       + g4_s[(64 + r) * 17 + b]
                       + g4_s[(128 + r) * 17 + b]
                       + g4_s[(192 + r) * 17 + b];
            }
            float c  = c_s[q2 * BPB + b];
            c = sigf(gv4[1]) * c + sigf(gv4[0]) * tanhf_fast(gv4[2]);
            hval = sigf(gv4[3]) * tanhf_fast(c);
            c_s[q2 * BPB + b] = c;
            int u = ub * UPB + q2;
            if (t != TT - 1)
                d_hbuf[(t + 1) & 1][dir][bg][u * BPB + b] = hval;
            hallidx = (size_t)(dir * HH + u) * (BB * TT)
                    + (size_t)(bg * BPB + b) * TT + ts;
        }
        __syncthreads();                       // hbuf stores complete
        if (t != TT - 1) bar_arrive(gid);
        if (tid < 256) d_hallT[hallidx] = hval;   // off critical path
    }
}

// ---------------------------------------------------------------------------
// Kernel 3: em[row][k] = sum_f hT[f][row]*wc[k][f] + bc (R9, measured)
// ---------------------------------------------------------------------------
__global__ __launch_bounds__(256) void em_kernel(const float* __restrict__ wc,
                                                 const float* __restrict__ bc)
{
    __shared__ float wc_s[KT * 512];
    __shared__ float bc_s[KT];
    const int tid = threadIdx.x;
    for (int i = tid; i < KT * 512; i += 256) wc_s[i] = wc[i];
    if (tid < KT) bc_s[tid] = bc[tid];
    __syncthreads();

    const int row = blockIdx.x * 256 + tid;
    const float* hp = d_hallT + row;

    float acc[KT];
#pragma unroll
    for (int k = 0; k < KT; k++) acc[k] = 0.f;

#pragma unroll 8
    for (int f = 0; f < 512; f++) {
        float hv = __ldcg(hp + (size_t)f * (BB * TT));
#pragma unroll
        for (int k = 0; k < KT; k++) acc[k] += hv * wc_s[k * 512 + f];
    }
#pragma unroll
    for (int k = 0; k < KT; k++)
        d_em[(size_t)row * KT + k] = acc[k] + bc_s[k];
}

// ---------------------------------------------------------------------------
// Kernel 4: CRF (R9, measured).
// ---------------------------------------------------------------------------
#define CRF_SMEM_BYTES ((441 + 64 + TT * KT) * 4 + TT * KT + 256)

__global__ __launch_bounds__(128) void crf_kernel(const int* __restrict__ y,
                                                  const float* __restrict__ start,
                                                  const float* __restrict__ endv,
                                                  const float* __restrict__ trans,
                                                  float* __restrict__ out,
                                                  int out_elems)
{
    extern __shared__ float csm[];
    float* tr_s = csm;
    float* sc   = csm + 448;
    float* e_s  = csm + 512;
    unsigned char* bp_s = (unsigned char*)(e_s + TT * KT);

    const int b    = blockIdx.x & 63;
    const int mode = blockIdx.x >> 6;
    const int tid  = threadIdx.x;

    for (int i = tid; i < KT * KT; i += 128) tr_s[i] = trans[i];
    {
        const float4* src = (const float4*)(d_em + (size_t)b * TT * KT);
        float4* dst = (float4*)e_s;
        for (int i = tid; i < (TT * KT) / 4; i += 128) dst[i] = src[i];
    }
    __syncthreads();

    const int k = tid;

    if (mode == 0) {
        if (tid < 32) {
            if (k < KT) sc[k] = start[k] + e_s[k];
            __syncwarp();
            for (int t = 1; t < TT; t++) {
                float nb = 0.f; int bi = 0;
                if (k < KT) {
                    float best = -1e30f;
#pragma unroll
                    for (int kp = 0; kp < KT; kp++) {
                        float vs = sc[kp] + tr_s[kp * KT + k];
                        if (vs > best) { best = vs; bi = kp; }
                    }
                    nb = best + e_s[t * KT + k];
                }
                __syncwarp();
                if (k < KT) { sc[k] = nb; bp_s[t * KT + k] = (unsigned char)bi; }
                __syncwarp();
            }
            if (k < KT) sc[k] += endv[k];
            __syncwarp();
            if (k == 0) {
                float best = sc[0]; int last = 0;
                for (int i = 1; i < KT; i++)
                    if (sc[i] > best) { best = sc[i]; last = i; }
                int tag = last;
                out[b * TT + TT - 1] = (float)tag;
                for (int t = TT - 1; t >= 1; t--) {
                    tag = bp_s[t * KT + tag];
                    out[b * TT + t - 1] = (float)tag;
                }
            }
        }
    } else {
        if (tid < 32) {
            if (k < KT) sc[k] = start[k] + e_s[k];
            __syncwarp();
            for (int t = 1; t < TT; t++) {
                float na = 0.f;
                if (k < KT) {
                    float mx = -1e30f;
#pragma unroll
                    for (int kp = 0; kp < KT; kp++)
                        mx = fmaxf(mx, sc[kp] + tr_s[kp * KT + k]);
                    float s = 0.f;
#pragma unroll
                    for (int kp = 0; kp < KT; kp++)
                        s += __expf(sc[kp] + tr_s[kp * KT + k] - mx);
                    na = mx + __logf(s) + e_s[t * KT + k];
                }
                __syncwarp();
                if (k < KT) sc[k] = na;
                __syncwarp();
            }
            if (k < KT) sc[k] += endv[k];
        }
        __syncthreads();

        float part = 0.f;
        for (int t = 1 + tid; t < TT; t += 128) {
            int yp = y[b * TT + t - 1];
            int yc = y[b * TT + t];
            part += tr_s[yp * KT + yc] + e_s[t * KT + yc];
        }
#pragma unroll
        for (int o = 16; o; o >>= 1) part += __shfl_down_sync(0xffffffffu, part, o);
        __shared__ float red[4];
        if ((tid & 31) == 0) red[tid >> 5] = part;
        __syncthreads();

        if (tid == 0) {
            float num = red[0] + red[1] + red[2] + red[3];
            float mx = -1e30f;
            for (int i = 0; i < KT; i++) mx = fmaxf(mx, sc[i]);
            float s = 0.f;
            for (int i = 0; i < KT; i++) s += __expf(sc[i] - mx);
            float z = mx + __logf(s);
            int y0 = y[b * TT];
            int yl = y[b * TT + TT - 1];
            num += start[y0] + e_s[y0] + endv[yl];
            d_lossb[b] = num - z;
        }
    }
}

__global__ void fin_kernel(float* out, int out_elems)
{
    if (out_elems > BB * TT) {
        float s = 0.f;
        for (int i = 0; i < BB; i++) s += d_lossb[i];
        out[BB * TT] = s / (float)BB;
    }
}

// ---------------------------------------------------------------------------
extern "C" void kernel_launch(void* const* d_in, const int* in_sizes, int n_in,
                              void* d_out, int out_size)
{
    const int*   x     = (const int*)d_in[0];
    const int*   y     = (const int*)d_in[1];
    // d_in[2] = masks (all true)
    const float* emb   = (const float*)d_in[3];
    const float* wih_f = (const float*)d_in[4];
    const float* whh_f = (const float*)d_in[5];
    const float* b_f   = (const float*)d_in[6];
    const float* wih_b = (const float*)d_in[7];
    const float* whh_b = (const float*)d_in[8];
    const float* b_b   = (const float*)d_in[9];
    const float* wc    = (const float*)d_in[10];
    const float* bc    = (const float*)d_in[11];
    const float* start = (const float*)d_in[12];
    const float* endv  = (const float*)d_in[13];
    const float* trans = (const float*)d_in[14];
    float* out = (float*)d_out;

    const size_t lstm_smem = LSTM_SMEM_FLOATS * sizeof(float);
    cudaFuncSetAttribute(lstm_kernel,
                         cudaFuncAttributeMaxDynamicSharedMemorySize,
                         (int)lstm_smem);
    cudaFuncSetAttribute(crf_kernel,
                         cudaFuncAttributeMaxDynamicSharedMemorySize,
                         (int)CRF_SMEM_BYTES);

    bar_reset<<<1, 32>>>();
    pre_gemm<<<dim3(256, 8, 2), 256>>>(x, emb, wih_f, b_f, wih_b, b_b);
    nop_kernel<<<1, 32>>>();   // spacer: shifts lstm into ncu's fixed capture slot
    lstm_kernel<<<128, 1024, lstm_smem>>>(whh_f, whh_b);
    em_kernel<<<128, 256>>>(wc, bc);
    crf_kernel<<<128, 128, CRF_SMEM_BYTES>>>(y, start, endv, trans, out, out_size);
    fin_kernel<<<1, 1>>>(out, out_size);
}